// round 2
// baseline (speedup 1.0000x reference)
#include <cuda_runtime.h>

// Problem constants (fixed shapes from reference setup_inputs)
#define N_L    4096   // coarse cells
#define L      16     // fine points per cell
#define NT     16     // target points per cell
#define NV     4      // variables
#define NH_SZ  9      // neighbor cells per cell
#define KC     144    // candidates per (cell, target) = NH_SZ * L
#define DPAD   145    // padded dist row (145*t mod 32 distinct for t=0..7)

#define MASK_VALUE   1.0e6f
#define CUTOFF_DIST  0.01f
#define BIG          3.0e38f

__global__ __launch_bounds__(128, 8)
void interp_kernel(const float* __restrict__ x,
                   const float* __restrict__ mask,
                   const float* __restrict__ dist,
                   const int*   __restrict__ nh_idx,
                   float*       __restrict__ out) {
    __shared__ float sd[NT * DPAD];    // dist tile, padded rows
    __shared__ float sx[KC * NV];      // gathered neighbor features
    __shared__ float sm[KC * NV];      // gathered mask * 1e6

    const int c   = blockIdx.x;
    const int tid = threadIdx.x;

    // ---- Phase 1a: stage dist[c, :, :] (2304 floats, coalesced) ----
    const float* dc = dist + (size_t)c * (NT * KC);
    #pragma unroll
    for (int i = tid; i < NT * KC; i += 128) {
        int t = i / KC;
        int k = i - t * KC;
        sd[t * DPAD + k] = dc[i];
    }

    // ---- Phase 1b: gather 9 neighbor cells' features + masks (576 each) ----
    #pragma unroll
    for (int i = tid; i < NH_SZ * L * NV; i += 128) {
        int j  = i / (L * NV);               // neighbor slot 0..8
        int r  = i - j * (L * NV);           // (li*NV + v) within cell
        int nc = nh_idx[c * NH_SZ + j];      // source cell
        int src = nc * (L * NV) + r;
        sx[i] = x[src];
        sm[i] = mask[src] * MASK_VALUE;
    }
    __syncthreads();

    // ---- Phase 2: 64 threads, one per (target, variable) ----
    if (tid < NT * NV) {
        const int t = tid >> 2;
        const int v = tid & 3;

        float d0 = BIG, d1 = BIG, d2 = BIG;
        float x0 = 0.f, x1 = 0.f, x2 = 0.f;
        const float* drow = sd + t * DPAD;

        #pragma unroll 4
        for (int k = 0; k < KC; k++) {
            float d  = drow[k] + sm[k * NV + v];
            float xv = sx[k * NV + v];
            // strict < preserves jax top_k's lower-index tie-break
            if (d < d2) {
                if (d < d1) {
                    d2 = d1; x2 = x1;
                    if (d < d0) { d1 = d0; x1 = x0; d0 = d; x0 = xv; }
                    else        { d1 = d;  x1 = xv; }
                } else {
                    d2 = d; x2 = xv;
                }
            }
        }

        d0 = fmaxf(d0, CUTOFF_DIST);
        d1 = fmaxf(d1, CUTOFF_DIST);
        d2 = fmaxf(d2, CUTOFF_DIST);
        float w0 = 1.0f / (d0 * d0);
        float w1 = 1.0f / (d1 * d1);
        float w2 = 1.0f / (d2 * d2);
        float inv_s = 1.0f / (w0 + w1 + w2);
        out[((size_t)c * NT + t) * NV + v] =
            (x0 * w0 + x1 * w1 + x2 * w2) * inv_s;
    }
}

extern "C" void kernel_launch(void* const* d_in, const int* in_sizes, int n_in,
                              void* d_out, int out_size) {
    const float* x      = (const float*)d_in[0];
    const float* mask   = (const float*)d_in[1];
    const float* dist   = (const float*)d_in[2];
    const int*   nh_idx = (const int*)  d_in[3];
    float*       out    = (float*)d_out;

    interp_kernel<<<N_L, 128>>>(x, mask, dist, nh_idx, out);
}

// round 3
// speedup vs baseline: 1.3939x; 1.3939x over previous
#include <cuda_runtime.h>

// Fixed problem shapes (from reference setup_inputs)
#define N_L    4096   // coarse cells
#define L      16     // fine points per cell
#define NT     16     // target points per cell
#define NV     4      // variables
#define NH_SZ  9      // neighbor cells
#define KC     144    // candidates per (cell,target)
#define DPAD   148    // padded dist row (multiple of 4 -> aligned float4 stores)

#define MASK_VALUE   1.0e6f
#define CUTOFF_DIST  0.01f
#define BIG          3.0e38f

// Branchless 3-slot insert, strict < (within a thread, indices increase, so
// strict < == lexicographic (d, idx) tie-break of jax top_k).
__device__ __forceinline__ void ins_scan(float d, int k,
    float& d0, int& k0, float& d1, int& k1, float& d2, int& k2) {
    bool b0 = d < d0, b1 = d < d1, b2 = d < d2;
    float nd2 = b1 ? d1 : (b2 ? d : d2);  int nk2 = b1 ? k1 : (b2 ? k : k2);
    float nd1 = b0 ? d0 : (b1 ? d : d1);  int nk1 = b0 ? k0 : (b1 ? k : k1);
    d0 = b0 ? d : d0;  k0 = b0 ? k : k0;
    d1 = nd1; k1 = nk1; d2 = nd2; k2 = nk2;
}

// Lexicographic (d, idx) insert for cross-thread merges.
__device__ __forceinline__ void ins_lex(float d, int k,
    float& d0, int& k0, float& d1, int& k1, float& d2, int& k2) {
    bool b0 = (d < d0) || (d == d0 && k < k0);
    bool b1 = (d < d1) || (d == d1 && k < k1);
    bool b2 = (d < d2) || (d == d2 && k < k2);
    float nd2 = b1 ? d1 : (b2 ? d : d2);  int nk2 = b1 ? k1 : (b2 ? k : k2);
    float nd1 = b0 ? d0 : (b1 ? d : d1);  int nk1 = b0 ? k0 : (b1 ? k : k1);
    d0 = b0 ? d : d0;  k0 = b0 ? k : k0;
    d1 = nd1; k1 = nk1; d2 = nd2; k2 = nk2;
}

__global__ __launch_bounds__(128, 8)
void interp_kernel(const float* __restrict__ x,
                   const float* __restrict__ mask,
                   const float* __restrict__ dist,
                   const int*   __restrict__ nh_idx,
                   float*       __restrict__ out) {
    __shared__ float  sd[NT * DPAD];   // dist tile (padded rows)
    __shared__ float4 sx4[KC];         // gathered features, [k] -> (v0..v3)
    __shared__ float4 sm4[KC];         // gathered mask * 1e6
    __shared__ int    sflag;           // any nonzero mask in this block?

    const int c   = blockIdx.x;
    const int tid = threadIdx.x;
    if (tid == 0) sflag = 0;

    // ---- Stage dist[c] : 2304 floats as 576 float4 (fully coalesced) ----
    const float4* d4 = (const float4*)(dist + (size_t)c * (NT * KC));
    #pragma unroll
    for (int i = tid; i < NT * KC / 4; i += 128) {
        int t = i / (KC / 4);
        int m = i - t * (KC / 4);
        *(float4*)&sd[t * DPAD + m * 4] = d4[i];
    }

    // ---- Gather 9 neighbor cells: x and mask, float4 ----
    bool any = false;
    const float4* x4p = (const float4*)x;
    const float4* m4p = (const float4*)mask;
    #pragma unroll
    for (int i = tid; i < KC; i += 128) {
        int j  = i >> 4;                 // neighbor slot
        int r  = i & 15;                 // fine point within cell
        int nc = nh_idx[c * NH_SZ + j];
        float4 xv = x4p[nc * 16 + r];
        float4 mv = m4p[nc * 16 + r];
        sx4[i] = xv;
        any |= (mv.x != 0.f) | (mv.y != 0.f) | (mv.z != 0.f) | (mv.w != 0.f);
        mv.x *= MASK_VALUE; mv.y *= MASK_VALUE;
        mv.z *= MASK_VALUE; mv.w *= MASK_VALUE;
        sm4[i] = mv;
    }
    __syncthreads();
    if (any) sflag = 1;
    __syncthreads();

    const float* sx = (const float*)sx4;
    const float* sm = (const float*)sm4;

    if (sflag == 0) {
        // ======== FAST PATH: mask == 0 -> top-3 independent of v ========
        // 8 threads per target t; warp w covers t = 4w..4w+3.
        const int lane = tid & 31;
        const int w    = tid >> 5;
        const int t    = w * 4 + (lane >> 3);
        const int sub  = lane & 7;
        const int base = sub * 18;       // contiguous k-range -> clean tie order
        const float* dr = sd + t * DPAD + base;

        float d0 = BIG, d1 = BIG, d2 = BIG;
        int   k0 = 0,   k1 = 0,   k2 = 0;
        #pragma unroll
        for (int i = 0; i < 18; i++)
            ins_scan(dr[i], base + i, d0, k0, d1, k1, d2, k2);

        // merge top-3 across the 8 threads of this target
        #pragma unroll
        for (int m = 1; m < 8; m <<= 1) {
            float pd0 = __shfl_xor_sync(0xffffffffu, d0, m);
            float pd1 = __shfl_xor_sync(0xffffffffu, d1, m);
            float pd2 = __shfl_xor_sync(0xffffffffu, d2, m);
            int   pk0 = __shfl_xor_sync(0xffffffffu, k0, m);
            int   pk1 = __shfl_xor_sync(0xffffffffu, k1, m);
            int   pk2 = __shfl_xor_sync(0xffffffffu, k2, m);
            ins_lex(pd0, pk0, d0, k0, d1, k1, d2, k2);
            ins_lex(pd1, pk1, d0, k0, d1, k1, d2, k2);
            ins_lex(pd2, pk2, d0, k0, d1, k1, d2, k2);
        }

        if (sub < NV) {
            const int v = sub;
            float a0 = fmaxf(d0, CUTOFF_DIST);
            float a1 = fmaxf(d1, CUTOFF_DIST);
            float a2 = fmaxf(d2, CUTOFF_DIST);
            // w_i = 1/a_i^2 normalized  ==  (a_j a_k)^2 / sum
            float q0 = a1 * a2, q1 = a0 * a2, q2 = a0 * a1;
            q0 *= q0; q1 *= q1; q2 *= q2;
            float g0 = sx[k0 * NV + v];
            float g1 = sx[k1 * NV + v];
            float g2 = sx[k2 * NV + v];
            out[(size_t)c * (NT * NV) + t * NV + v] =
                (g0 * q0 + g1 * q1 + g2 * q2) / (q0 + q1 + q2);
        }
    } else {
        // ======== SLOW PATH: general mask, one thread per (t, v) ========
        if (tid < NT * NV) {
            const int t = tid >> 2;
            const int v = tid & 3;
            const float* dr = sd + t * DPAD;
            float d0 = BIG, d1 = BIG, d2 = BIG;
            int   k0 = 0,   k1 = 0,   k2 = 0;
            #pragma unroll 4
            for (int k = 0; k < KC; k++) {
                float d = dr[k] + sm[k * NV + v];
                ins_scan(d, k, d0, k0, d1, k1, d2, k2);
            }
            float a0 = fmaxf(d0, CUTOFF_DIST);
            float a1 = fmaxf(d1, CUTOFF_DIST);
            float a2 = fmaxf(d2, CUTOFF_DIST);
            float q0 = a1 * a2, q1 = a0 * a2, q2 = a0 * a1;
            q0 *= q0; q1 *= q1; q2 *= q2;
            float g0 = sx[k0 * NV + v];
            float g1 = sx[k1 * NV + v];
            float g2 = sx[k2 * NV + v];
            out[(size_t)c * (NT * NV) + t * NV + v] =
                (g0 * q0 + g1 * q1 + g2 * q2) / (q0 + q1 + q2);
        }
    }
}

extern "C" void kernel_launch(void* const* d_in, const int* in_sizes, int n_in,
                              void* d_out, int out_size) {
    const float* x      = (const float*)d_in[0];
    const float* mask   = (const float*)d_in[1];
    const float* dist   = (const float*)d_in[2];
    const int*   nh_idx = (const int*)  d_in[3];
    float*       out    = (float*)d_out;

    interp_kernel<<<N_L, 128>>>(x, mask, dist, nh_idx, out);
}

// round 4
// speedup vs baseline: 1.7763x; 1.2743x over previous
#include <cuda_runtime.h>

// Fixed problem shapes (from reference setup_inputs)
#define N_L    4096
#define L      16
#define NT     16
#define NV     4
#define NH_SZ  9
#define KC     144          // candidates per (cell,target)
#define DPAD   168          // 168 % 32 == 8 -> conflict-free interleaved scan
#define CAP    8            // per-target recovery list capacity

#define MASK_VALUE   1.0e6f
#define CUTOFF_DIST  0.01f
#define BIG          3.0e38f

// Insert value d into sorted triple (s0<=s1<=s2). 5 FMNMX, exact.
#define VINS(d, s0, s1, s2) do {            \
    float _t1 = fmaxf(s0, (d)); s0 = fminf(s0, (d)); \
    float _t2 = fmaxf(s1, _t1); s1 = fminf(s1, _t1); \
    s2 = fminf(s2, _t2);                     \
} while (0)

// Lowest-3 of two sorted triples -> (c0,c1,c2). 9 FMNMX, exact.
#define MERGE3(a0,a1,a2,b0,b1,b2,c0,c1,c2) do { \
    c0 = fminf(a0, b0);                          \
    float _x = fmaxf(a0, b0);                    \
    c1 = fminf(_x, fminf(a1, b1));               \
    c2 = fminf(fminf(a2, b2),                    \
               fminf(fmaxf(a1, b0), fmaxf(a0, b1))); \
} while (0)

// Lexicographic u64-key insert into 3 smallest.
__device__ __forceinline__ void kins(unsigned long long key,
    unsigned long long& q0, unsigned long long& q1, unsigned long long& q2) {
    bool b0 = key < q0, b1 = key < q1, b2 = key < q2;
    unsigned long long n2 = b1 ? q1 : (b2 ? key : q2);
    unsigned long long n1 = b0 ? q0 : (b1 ? key : q1);
    q0 = b0 ? key : q0;
    q1 = n1; q2 = n2;
}

// (value,index) lex insert for slow path.
__device__ __forceinline__ void ins_lex(float d, int k,
    float& d0, int& k0, float& d1, int& k1, float& d2, int& k2) {
    bool b0 = (d < d0) || (d == d0 && k < k0);
    bool b1 = (d < d1) || (d == d1 && k < k1);
    bool b2 = (d < d2) || (d == d2 && k < k2);
    float nd2 = b1 ? d1 : (b2 ? d : d2);  int nk2 = b1 ? k1 : (b2 ? k : k2);
    float nd1 = b0 ? d0 : (b1 ? d : d1);  int nk1 = b0 ? k0 : (b1 ? k : k1);
    d0 = b0 ? d : d0;  k0 = b0 ? k : k0;
    d1 = nd1; k1 = nk1; d2 = nd2; k2 = nk2;
}

__global__ __launch_bounds__(128, 12)
void interp_kernel(const float* __restrict__ x,
                   const float* __restrict__ mask,
                   const float* __restrict__ dist,
                   const int*   __restrict__ nh_idx,
                   float*       __restrict__ out) {
    __shared__ float  sd[NT * DPAD];
    __shared__ float4 sx4[KC];
    __shared__ unsigned long long slist[NT][CAP];
    __shared__ int  scnt[NT];
    __shared__ int  sflag;

    const int c   = blockIdx.x;
    const int tid = threadIdx.x;
    if (tid < NT) scnt[tid] = 0;
    if (tid == 0) sflag = 0;

    // ---- Stage dist[c]: 576 float4, coalesced ----
    const float4* d4 = (const float4*)(dist + (size_t)c * (NT * KC));
    #pragma unroll
    for (int i = tid; i < NT * KC / 4; i += 128) {
        int t = i / (KC / 4);
        int m = i - t * (KC / 4);
        *(float4*)&sd[t * DPAD + m * 4] = d4[i];
    }

    // ---- Gather 9 neighbor cells' features; detect nonzero mask ----
    bool any = false;
    const float4* x4p = (const float4*)x;
    const float4* m4p = (const float4*)mask;
    #pragma unroll
    for (int i = tid; i < KC; i += 128) {
        int j  = i >> 4;
        int r  = i & 15;
        int nc = nh_idx[c * NH_SZ + j];
        sx4[i] = x4p[nc * 16 + r];
        float4 mv = m4p[nc * 16 + r];
        any |= (mv.x != 0.f) | (mv.y != 0.f) | (mv.z != 0.f) | (mv.w != 0.f);
    }
    __syncthreads();
    if (any) sflag = 1;
    __syncthreads();

    const float* sx = (const float*)sx4;

    if (sflag == 0) {
        // ================= FAST PATH (mask == 0) =================
        const int lane = tid & 31;
        const int w    = tid >> 5;
        const int t    = w * 4 + (lane >> 3);   // 8 lanes per target, warp-aligned
        const int sub  = lane & 7;
        const float* dr = sd + t * DPAD + sub;  // interleaved: k = sub + 8*i

        // --- value-only sorted-3, two interleaved streams for ILP ---
        float a0 = BIG, a1 = BIG, a2 = BIG;
        float b0 = BIG, b1 = BIG, b2 = BIG;
        #pragma unroll
        for (int i = 0; i < 18; i += 2) {
            VINS(dr[8 * i],       a0, a1, a2);
            VINS(dr[8 * (i + 1)], b0, b1, b2);
        }
        float d0, d1, d2;
        MERGE3(a0, a1, a2, b0, b1, b2, d0, d1, d2);

        // --- merge across the 8 threads of this target ---
        #pragma unroll
        for (int m = 1; m < 8; m <<= 1) {
            float p0 = __shfl_xor_sync(0xffffffffu, d0, m);
            float p1 = __shfl_xor_sync(0xffffffffu, d1, m);
            float p2 = __shfl_xor_sync(0xffffffffu, d2, m);
            float e0, e1, e2;
            MERGE3(d0, d1, d2, p0, p1, p2, e0, e1, e2);
            d0 = e0; d1 = e1; d2 = e2;
        }

        // --- exact index recovery: push candidates <= d2 ---
        unsigned mbits = 0;
        #pragma unroll
        for (int i = 0; i < 18; i++)
            mbits |= (dr[8 * i] <= d2) ? (1u << i) : 0u;
        while (mbits) {
            int i = __ffs(mbits) - 1;
            mbits &= mbits - 1;
            int k = sub + 8 * i;
            int idx = atomicAdd(&scnt[t], 1);
            if (idx < CAP) {
                float v = sd[t * DPAD + k];
                slist[t][idx] =
                    ((unsigned long long)__float_as_uint(v) << 8) | (unsigned)k;
            }
        }
        __syncwarp();

        if (sub < NV) {
            const int v = sub;
            int n = scnt[t];
            unsigned long long q0 = ~0ull, q1 = ~0ull, q2 = ~0ull;
            if (n <= CAP) {
                for (int i = 0; i < n; i++)
                    kins(slist[t][i], q0, q1, q2);
            } else {
                // degenerate tie overflow: exact full rescan (never taken in practice)
                const float* row = sd + t * DPAD;
                for (int k = 0; k < KC; k++) {
                    unsigned long long key =
                        ((unsigned long long)__float_as_uint(row[k]) << 8) | (unsigned)k;
                    kins(key, q0, q1, q2);
                }
            }
            float f0 = __uint_as_float((unsigned)(q0 >> 8));
            float f1 = __uint_as_float((unsigned)(q1 >> 8));
            float f2 = __uint_as_float((unsigned)(q2 >> 8));
            int   i0 = (int)(q0 & 0xFF), i1 = (int)(q1 & 0xFF), i2 = (int)(q2 & 0xFF);

            float c0 = fmaxf(f0, CUTOFF_DIST);
            float c1 = fmaxf(f1, CUTOFF_DIST);
            float c2 = fmaxf(f2, CUTOFF_DIST);
            float w0 = c1 * c2, w1 = c0 * c2, w2 = c0 * c1;
            w0 *= w0; w1 *= w1; w2 *= w2;
            float g0 = sx[i0 * NV + v];
            float g1 = sx[i1 * NV + v];
            float g2 = sx[i2 * NV + v];
            out[(size_t)c * (NT * NV) + t * NV + v] =
                (g0 * w0 + g1 * w1 + g2 * w2) / (w0 + w1 + w2);
        }
    } else {
        // ================= SLOW PATH (general mask) =================
        if (tid < NT * NV) {
            const int t = tid >> 2;
            const int v = tid & 3;
            const float* dr = sd + t * DPAD;
            float d0 = BIG, d1 = BIG, d2 = BIG;
            int   k0 = 0,   k1 = 0,   k2 = 0;
            for (int k = 0; k < KC; k++) {
                int j  = k >> 4;
                int r  = k & 15;
                int nc = nh_idx[c * NH_SZ + j];
                float mk = mask[(nc * 16 + r) * NV + v] * MASK_VALUE;
                float d  = dr[k] + mk;
                ins_lex(d, k, d0, k0, d1, k1, d2, k2);
            }
            float c0 = fmaxf(d0, CUTOFF_DIST);
            float c1 = fmaxf(d1, CUTOFF_DIST);
            float c2 = fmaxf(d2, CUTOFF_DIST);
            float w0 = c1 * c2, w1 = c0 * c2, w2 = c0 * c1;
            w0 *= w0; w1 *= w1; w2 *= w2;
            float g0 = sx[k0 * NV + v];
            float g1 = sx[k1 * NV + v];
            float g2 = sx[k2 * NV + v];
            out[(size_t)c * (NT * NV) + t * NV + v] =
                (g0 * w0 + g1 * w1 + g2 * w2) / (w0 + w1 + w2);
        }
    }
}

extern "C" void kernel_launch(void* const* d_in, const int* in_sizes, int n_in,
                              void* d_out, int out_size) {
    const float* x      = (const float*)d_in[0];
    const float* mask   = (const float*)d_in[1];
    const float* dist   = (const float*)d_in[2];
    const int*   nh_idx = (const int*)  d_in[3];
    float*       out    = (float*)d_out;

    interp_kernel<<<N_L, 128>>>(x, mask, dist, nh_idx, out);
}

// round 5
// speedup vs baseline: 1.9762x; 1.1126x over previous
#include <cuda_runtime.h>

// Fixed problem shapes (from reference setup_inputs)
#define N_L    4096
#define L      16
#define NT     16
#define NV     4
#define NH_SZ  9
#define KC     144          // candidates per (cell,target)
#define CAP    8            // per-target recovery list capacity

#define MASK_VALUE   1.0e6f
#define CUTOFF_DIST  0.01f
#define BIG          3.0e38f

// Insert value d into sorted triple (s0<=s1<=s2). 5 FMNMX, exact.
#define VINS(d, s0, s1, s2) do {                     \
    float _t1 = fmaxf(s0, (d)); s0 = fminf(s0, (d)); \
    float _t2 = fmaxf(s1, _t1); s1 = fminf(s1, _t1); \
    s2 = fminf(s2, _t2);                             \
} while (0)

// Lowest-3 of two sorted triples -> (c0<=c1<=c2). 9 FMNMX, exact.
#define MERGE3(a0,a1,a2,b0,b1,b2,c0,c1,c2) do {      \
    c0 = fminf(a0, b0);                              \
    float _x = fmaxf(a0, b0);                        \
    c1 = fminf(_x, fminf(a1, b1));                   \
    c2 = fminf(fminf(a2, b2),                        \
               fminf(fmaxf(a1, b0), fmaxf(a0, b1))); \
} while (0)

// Lexicographic u64-key insert into 3 smallest.
__device__ __forceinline__ void kins(unsigned long long key,
    unsigned long long& q0, unsigned long long& q1, unsigned long long& q2) {
    bool b0 = key < q0, b1 = key < q1, b2 = key < q2;
    unsigned long long n2 = b1 ? q1 : (b2 ? key : q2);
    unsigned long long n1 = b0 ? q0 : (b1 ? key : q1);
    q0 = b0 ? key : q0;
    q1 = n1; q2 = n2;
}

// (value,index) lex insert for slow path.
__device__ __forceinline__ void ins_lex(float d, int k,
    float& d0, int& k0, float& d1, int& k1, float& d2, int& k2) {
    bool b0 = (d < d0) || (d == d0 && k < k0);
    bool b1 = (d < d1) || (d == d1 && k < k1);
    bool b2 = (d < d2) || (d == d2 && k < k2);
    float nd2 = b1 ? d1 : (b2 ? d : d2);  int nk2 = b1 ? k1 : (b2 ? k : k2);
    float nd1 = b0 ? d0 : (b1 ? d : d1);  int nk1 = b0 ? k0 : (b1 ? k : k1);
    d0 = b0 ? d : d0;  k0 = b0 ? k : k0;
    d1 = nd1; k1 = nk1; d2 = nd2; k2 = nk2;
}

__global__ __launch_bounds__(128, 10)
void interp_kernel(const float* __restrict__ x,
                   const float* __restrict__ mask,
                   const float* __restrict__ dist,
                   const int*   __restrict__ nh_idx,
                   float*       __restrict__ out) {
    __shared__ float4 sx4[KC];                       // gathered features
    __shared__ unsigned long long slist[NT][CAP];    // recovery lists
    __shared__ int scnt[NT];

    const int c    = blockIdx.x;
    const int tid  = threadIdx.x;
    const int lane = tid & 31;
    const int w    = tid >> 5;
    const int t    = w * 4 + (lane >> 3);   // 8 lanes per target, warp-aligned
    const int sub  = lane & 7;

    if (tid < NT) scnt[tid] = 0;

    // ---- dist candidates straight into registers (coalesced float4) ----
    // thread `sub` owns float4 columns {sub, sub+8, sub+16, sub+24} (+ sub+32 if sub<4)
    const float4* drow4 = (const float4*)(dist + (size_t)c * (NT * KC) + t * KC);
    float4 v0 = drow4[sub];
    float4 v1 = drow4[sub + 8];
    float4 v2 = drow4[sub + 16];
    float4 v3 = drow4[sub + 24];
    float4 v4 = make_float4(BIG, BIG, BIG, BIG);
    if (sub < 4) v4 = drow4[sub + 32];

    // ---- gather 9 neighbor cells' features; detect nonzero mask ----
    bool any = false;
    const float4* x4p = (const float4*)x;
    const float4* m4p = (const float4*)mask;
    #pragma unroll
    for (int i = tid; i < KC; i += 128) {
        int j  = i >> 4;
        int r  = i & 15;
        int nc = nh_idx[c * NH_SZ + j];
        sx4[i] = x4p[nc * 16 + r];
        float4 mv = m4p[nc * 16 + r];
        any |= (mv.x != 0.f) | (mv.y != 0.f) | (mv.z != 0.f) | (mv.w != 0.f);
    }

    // ---- speculative value-only scan, 4 ILP streams (one per component) ----
    float ax = BIG, bx = BIG, cx = BIG;
    float ay = BIG, by = BIG, cy = BIG;
    float az = BIG, bz = BIG, cz = BIG;
    float aw = BIG, bw = BIG, cw = BIG;
    VINS(v0.x, ax, bx, cx); VINS(v0.y, ay, by, cy);
    VINS(v0.z, az, bz, cz); VINS(v0.w, aw, bw, cw);
    VINS(v1.x, ax, bx, cx); VINS(v1.y, ay, by, cy);
    VINS(v1.z, az, bz, cz); VINS(v1.w, aw, bw, cw);
    VINS(v2.x, ax, bx, cx); VINS(v2.y, ay, by, cy);
    VINS(v2.z, az, bz, cz); VINS(v2.w, aw, bw, cw);
    VINS(v3.x, ax, bx, cx); VINS(v3.y, ay, by, cy);
    VINS(v3.z, az, bz, cz); VINS(v3.w, aw, bw, cw);
    VINS(v4.x, ax, bx, cx); VINS(v4.y, ay, by, cy);
    VINS(v4.z, az, bz, cz); VINS(v4.w, aw, bw, cw);

    float mx0, mx1, mx2, my0, my1, my2;
    MERGE3(ax, bx, cx, ay, by, cy, mx0, mx1, mx2);
    MERGE3(az, bz, cz, aw, bw, cw, my0, my1, my2);
    float d0, d1, d2;
    MERGE3(mx0, mx1, mx2, my0, my1, my2, d0, d1, d2);

    // ---- merge across the 8 threads of this target ----
    #pragma unroll
    for (int m = 1; m < 8; m <<= 1) {
        float p0 = __shfl_xor_sync(0xffffffffu, d0, m);
        float p1 = __shfl_xor_sync(0xffffffffu, d1, m);
        float p2 = __shfl_xor_sync(0xffffffffu, d2, m);
        float e0, e1, e2;
        MERGE3(d0, d1, d2, p0, p1, p2, e0, e1, e2);
        d0 = e0; d1 = e1; d2 = e2;
    }

    // one barrier: publishes sx4/scnt AND reduces the mask flag
    int bad = __syncthreads_or(any ? 1 : 0);

    const float* sx = (const float*)sx4;

    if (!bad) {
        // ================= FAST PATH (mask == 0) =================
        // exact index recovery from registers: push candidates <= d2
        #define TRYC(val, kk) do {                                          \
            if ((val) <= d2) {                                              \
                int _i = atomicAdd(&scnt[t], 1);                            \
                if (_i < CAP)                                               \
                    slist[t][_i] = ((unsigned long long)__float_as_uint(val) \
                                    << 8) | (unsigned)(kk);                 \
            } } while (0)
        int kb = 4 * sub;
        TRYC(v0.x, kb);       TRYC(v0.y, kb + 1);
        TRYC(v0.z, kb + 2);   TRYC(v0.w, kb + 3);
        TRYC(v1.x, kb + 32);  TRYC(v1.y, kb + 33);
        TRYC(v1.z, kb + 34);  TRYC(v1.w, kb + 35);
        TRYC(v2.x, kb + 64);  TRYC(v2.y, kb + 65);
        TRYC(v2.z, kb + 66);  TRYC(v2.w, kb + 67);
        TRYC(v3.x, kb + 96);  TRYC(v3.y, kb + 97);
        TRYC(v3.z, kb + 98);  TRYC(v3.w, kb + 99);
        if (sub < 4) {
            TRYC(v4.x, kb + 128); TRYC(v4.y, kb + 129);
            TRYC(v4.z, kb + 130); TRYC(v4.w, kb + 131);
        }
        #undef TRYC
        __syncwarp();   // pushes for target t all come from this warp

        if (sub < NV) {
            const int v = sub;
            int n = scnt[t];
            unsigned long long q0 = ~0ull, q1 = ~0ull, q2 = ~0ull;
            if (n <= CAP) {
                for (int i = 0; i < n; i++)
                    kins(slist[t][i], q0, q1, q2);
            } else {
                // degenerate tie overflow: exact full rescan from global
                const float* row = dist + (size_t)c * (NT * KC) + t * KC;
                for (int k = 0; k < KC; k++) {
                    unsigned long long key =
                        ((unsigned long long)__float_as_uint(row[k]) << 8)
                        | (unsigned)k;
                    kins(key, q0, q1, q2);
                }
            }
            float f0 = __uint_as_float((unsigned)(q0 >> 8));
            float f1 = __uint_as_float((unsigned)(q1 >> 8));
            float f2 = __uint_as_float((unsigned)(q2 >> 8));
            int   i0 = (int)(q0 & 0xFF), i1 = (int)(q1 & 0xFF),
                  i2 = (int)(q2 & 0xFF);

            float c0 = fmaxf(f0, CUTOFF_DIST);
            float c1 = fmaxf(f1, CUTOFF_DIST);
            float c2 = fmaxf(f2, CUTOFF_DIST);
            float w0 = c1 * c2, w1 = c0 * c2, w2 = c0 * c1;
            w0 *= w0; w1 *= w1; w2 *= w2;
            float g0 = sx[i0 * NV + v];
            float g1 = sx[i1 * NV + v];
            float g2 = sx[i2 * NV + v];
            out[(size_t)c * (NT * NV) + t * NV + v] =
                (g0 * w0 + g1 * w1 + g2 * w2) / (w0 + w1 + w2);
        }
    } else {
        // ================= SLOW PATH (general mask) =================
        if (tid < NT * NV) {
            const int tt = tid >> 2;
            const int v  = tid & 3;
            const float* dr = dist + (size_t)c * (NT * KC) + tt * KC;
            float s0 = BIG, s1 = BIG, s2 = BIG;
            int   k0 = 0,   k1 = 0,   k2 = 0;
            for (int k = 0; k < KC; k++) {
                int j  = k >> 4;
                int r  = k & 15;
                int nc = nh_idx[c * NH_SZ + j];
                float mk = mask[(nc * 16 + r) * NV + v] * MASK_VALUE;
                float d  = dr[k] + mk;
                ins_lex(d, k, s0, k0, s1, k1, s2, k2);
            }
            float c0 = fmaxf(s0, CUTOFF_DIST);
            float c1 = fmaxf(s1, CUTOFF_DIST);
            float c2 = fmaxf(s2, CUTOFF_DIST);
            float w0 = c1 * c2, w1 = c0 * c2, w2 = c0 * c1;
            w0 *= w0; w1 *= w1; w2 *= w2;
            float g0 = sx[k0 * NV + v];
            float g1 = sx[k1 * NV + v];
            float g2 = sx[k2 * NV + v];
            out[(size_t)c * (NT * NV) + tt * NV + v] =
                (g0 * w0 + g1 * w1 + g2 * w2) / (w0 + w1 + w2);
        }
    }
}

extern "C" void kernel_launch(void* const* d_in, const int* in_sizes, int n_in,
                              void* d_out, int out_size) {
    const float* x      = (const float*)d_in[0];
    const float* mask   = (const float*)d_in[1];
    const float* dist   = (const float*)d_in[2];
    const int*   nh_idx = (const int*)  d_in[3];
    float*       out    = (float*)d_out;

    interp_kernel<<<N_L, 128>>>(x, mask, dist, nh_idx, out);
}